// round 1
// baseline (speedup 1.0000x reference)
#include <cuda_runtime.h>
#include <math.h>

// ---------------------------------------------------------------------------
// Causal self-attention block, fp32 baseline.
//   B=4, T=2048, C=1024. M = B*T = 8192.
//   Pipeline: qkv GEMM -> scores GEMM (causal tile-skip) -> softmax ->
//             att@V GEMM (k-limited) -> out proj GEMM.
// Scratch via __device__ globals (allocation is banned in kernel_launch).
// ---------------------------------------------------------------------------

#define BM 128
#define BN 128
#define BK 8

// [M, 3C] = [8192, 3072]
__device__ float g_qkv[8192 * 3072];
// [B, T, T] = [4, 2048, 2048]
__device__ float g_att[4 * 2048 * 2048];
// [M, C] = [8192, 1024]
__device__ float g_o[8192 * 1024];

// C = alpha * A * op(B) + bias
//  BT=true : B is [N, K] row-major (computes A * B^T)   -- x@W^T, Q@K^T
//  BT=false: B is [K, N] row-major (computes A * B)     -- att@V
// causal_skip: skip tiles entirely above the diagonal (scores)
// klimit:      only accumulate k < row0+BM (att@V causal pruning)
template <bool BT>
__global__ __launch_bounds__(256, 2)
void gemm_kernel(const float* __restrict__ A, const float* __restrict__ B,
                 float* __restrict__ C,
                 int M, int N, int K, int lda, int ldb, int ldc,
                 long long sA, long long sB, long long sC,
                 float alpha, const float* __restrict__ bias,
                 int causal_skip, int klimit)
{
    const int row0 = blockIdx.y * BM;
    const int col0 = blockIdx.x * BN;
    if (causal_skip && col0 > row0 + BM - 1) return;   // strictly-upper tile
    const int kend = klimit ? min(K, row0 + BM) : K;

    A += (long long)blockIdx.z * sA;
    B += (long long)blockIdx.z * sB;
    C += (long long)blockIdx.z * sC;

    __shared__ float As[BK][BM + 4];
    __shared__ float Bs[BK][BN + 4];

    const int tid = threadIdx.x;
    const int tx = tid & 15;       // 0..15 -> N micro-tiles
    const int ty = tid >> 4;       // 0..15 -> M micro-tiles

    // A-tile load mapping (also used for B when BT): 128 rows x 8 k, float4
    const int ar = tid >> 1;            // 0..127
    const int ak = (tid & 1) * 4;       // 0 or 4
    // B-tile load mapping (nn): 8 k-rows x 128 cols, float4
    const int bk = tid >> 5;            // 0..7
    const int bc = (tid & 31) * 4;      // 0..124

    float acc[8][8];
    #pragma unroll
    for (int i = 0; i < 8; i++)
        #pragma unroll
        for (int j = 0; j < 8; j++) acc[i][j] = 0.f;

    const float* Aptr   = A + (long long)(row0 + ar) * lda + ak;
    const float* BptrNT = B + (long long)(col0 + ar) * ldb + ak;
    const float* BptrNN = B + (long long)bk * ldb + col0 + bc;
    const long long bnn_step = (long long)BK * ldb;

    for (int k0 = 0; k0 < kend; k0 += BK) {
        float4 av = *(const float4*)Aptr;
        As[ak + 0][ar] = av.x; As[ak + 1][ar] = av.y;
        As[ak + 2][ar] = av.z; As[ak + 3][ar] = av.w;
        if (BT) {
            float4 bv = *(const float4*)BptrNT;
            Bs[ak + 0][ar] = bv.x; Bs[ak + 1][ar] = bv.y;
            Bs[ak + 2][ar] = bv.z; Bs[ak + 3][ar] = bv.w;
            BptrNT += BK;
        } else {
            float4 bv = *(const float4*)BptrNN;
            *(float4*)&Bs[bk][bc] = bv;
            BptrNN += bnn_step;
        }
        Aptr += BK;
        __syncthreads();

        #pragma unroll
        for (int kk = 0; kk < BK; kk++) {
            float a[8], b[8];
            *(float4*)(a)     = *(const float4*)&As[kk][ty * 8];
            *(float4*)(a + 4) = *(const float4*)&As[kk][ty * 8 + 4];
            *(float4*)(b)     = *(const float4*)&Bs[kk][tx * 8];
            *(float4*)(b + 4) = *(const float4*)&Bs[kk][tx * 8 + 4];
            #pragma unroll
            for (int i = 0; i < 8; i++)
                #pragma unroll
                for (int j = 0; j < 8; j++)
                    acc[i][j] += a[i] * b[j];
        }
        __syncthreads();
    }

    #pragma unroll
    for (int i = 0; i < 8; i++) {
        const int r = row0 + ty * 8 + i;
        float* Crow = C + (long long)r * ldc + col0 + tx * 8;
        #pragma unroll
        for (int j = 0; j < 8; j += 4) {
            float4 v;
            v.x = acc[i][j + 0] * alpha;
            v.y = acc[i][j + 1] * alpha;
            v.z = acc[i][j + 2] * alpha;
            v.w = acc[i][j + 3] * alpha;
            if (bias) {
                const float* bp = bias + col0 + tx * 8 + j;
                v.x += bp[0]; v.y += bp[1]; v.z += bp[2]; v.w += bp[3];
            }
            *(float4*)(Crow + j) = v;
        }
    }
}

// In-place causal softmax over each att row; zeros the masked tail so the
// downstream nn-GEMM can read full k-tiles.
__global__ void softmax_kernel(float* __restrict__ att, int T)
{
    const int row = blockIdx.x;            // 0 .. B*T-1 (rows are contiguous)
    const int t = row % T;
    float* p = att + (long long)row * T;
    const int tid = threadIdx.x;
    const int len = t + 1;

    __shared__ float red[256];

    float m = -1e30f;
    for (int s = tid; s < len; s += 256) m = fmaxf(m, p[s]);
    red[tid] = m; __syncthreads();
    for (int off = 128; off > 0; off >>= 1) {
        if (tid < off) red[tid] = fmaxf(red[tid], red[tid + off]);
        __syncthreads();
    }
    m = red[0]; __syncthreads();

    float sum = 0.f;
    for (int s = tid; s < len; s += 256) {
        float e = __expf(p[s] - m);
        p[s] = e;
        sum += e;
    }
    red[tid] = sum; __syncthreads();
    for (int off = 128; off > 0; off >>= 1) {
        if (tid < off) red[tid] += red[tid + off];
        __syncthreads();
    }
    const float inv = 1.f / red[0];

    for (int s = tid; s < len; s += 256) p[s] *= inv;
    for (int s = len + tid; s < T; s += 256) p[s] = 0.f;
}

extern "C" void kernel_launch(void* const* d_in, const int* in_sizes, int n_in,
                              void* d_out, int out_size)
{
    const float* x      = (const float*)d_in[0];
    const float* w_qkv  = (const float*)d_in[1];
    const float* b_qkv  = (const float*)d_in[2];
    const float* w_proj = (const float*)d_in[3];
    const float* b_proj = (const float*)d_in[4];
    float* out = (float*)d_out;

    float *qkv, *att, *o;
    cudaGetSymbolAddress((void**)&qkv, g_qkv);
    cudaGetSymbolAddress((void**)&att, g_att);
    cudaGetSymbolAddress((void**)&o,   g_o);

    const int Bb = 4, T = 2048, C = 1024;
    const int M = Bb * T;                      // 8192
    const float inv_sqrt_c = 0.03125f;         // 1/sqrt(1024)

    // 1) qkv = x @ w_qkv^T + b_qkv        [8192, 3072]
    {
        dim3 g(3 * C / BN, M / BM, 1);
        gemm_kernel<true><<<g, 256>>>(x, w_qkv, qkv,
            M, 3 * C, C, C, C, 3 * C,
            0, 0, 0, 1.f, b_qkv, 0, 0);
    }
    // 2) scores = (Q @ K^T) / sqrt(C)     per batch, causal tile-skip
    {
        dim3 g(T / BN, T / BM, Bb);
        gemm_kernel<true><<<g, 256>>>(qkv, qkv + C, att,
            T, T, C, 3 * C, 3 * C, T,
            (long long)T * 3 * C, (long long)T * 3 * C, (long long)T * T,
            inv_sqrt_c, nullptr, 1, 0);
    }
    // 3) causal softmax, in place (zeros masked tail)
    softmax_kernel<<<M, 256>>>(att, T);
    // 4) o = att @ V                      per batch, k-limited by causality
    {
        dim3 g(C / BN, T / BM, Bb);
        gemm_kernel<false><<<g, 256>>>(att, qkv + 2 * C, o,
            T, C, T, T, 3 * C, C,
            (long long)T * T, (long long)T * 3 * C, (long long)T * C,
            1.f, nullptr, 0, 1);
    }
    // 5) out = o @ w_proj^T + b_proj      [8192, 1024]
    {
        dim3 g(C / BN, M / BM, 1);
        gemm_kernel<true><<<g, 256>>>(o, w_proj, out,
            M, C, C, C, C, C,
            0, 0, 0, 1.f, b_proj, 0, 0);
    }
}

// round 4
// speedup vs baseline: 2.2264x; 2.2264x over previous
#include <cuda_runtime.h>
#include <cuda_bf16.h>
#include <math.h>

// ---------------------------------------------------------------------------
// Causal self-attention block via mma.sync (HMMA bf16) on sm_103.
// fp32 emulation by 3-term bf16 split along K (k' = 3k + {0,1,2}):
//   A3 = (Ah, Al, Ah),  B3 = (Bh, Bh, Bl)
//   sum_k' A3 B3 = Ah·Bh + Al·Bh + Ah·Bl   (drops only Al·Bl ~ 2^-18)
// fp32 accumulation in HMMA -> rel err ~1e-5.
// ---------------------------------------------------------------------------

static const int Bb = 4, T = 2048, C = 1024;
static const int M = Bb * T;          // 8192
static const int K3C = 3 * C;         // 3072
static const int K3T = 3 * T;         // 6144

// fp32 intermediates
__device__ float g_qkv[(size_t)8192 * 3072];
__device__ float g_att[(size_t)4 * 2048 * 2048];
__device__ float g_o  [(size_t)8192 * 1024];
// 3-split bf16 operands
__device__ __nv_bfloat16 g_x3    [(size_t)8192 * 3072];
__device__ __nv_bfloat16 g_wqkv3 [(size_t)3072 * 3072];
__device__ __nv_bfloat16 g_wproj3[(size_t)1024 * 3072];
__device__ __nv_bfloat16 g_q3    [(size_t)8192 * 3072];
__device__ __nv_bfloat16 g_k3    [(size_t)8192 * 3072];
__device__ __nv_bfloat16 g_vt3   [(size_t)4 * 1024 * 6144];
__device__ __nv_bfloat16 g_att3  [(size_t)8192 * 6144];
__device__ __nv_bfloat16 g_o3    [(size_t)8192 * 3072];

// 16B-chunk XOR swizzle: row r (64B rows), chunk c in 0..3.
#define SWOFF(r, c) ((unsigned)((r) * 64 + ((((c) ^ (((r) >> 1) & 3)) & 3) << 4)))

__device__ __forceinline__ void cp_async16(unsigned s, const void* g) {
    asm volatile("cp.async.cg.shared.global [%0], [%1], 16;"
        :: "r"(s), "l"(__cvta_generic_to_global(g)) : "memory");
}
__device__ __forceinline__ void ldm4(unsigned* r, unsigned addr) {
    asm volatile("ldmatrix.sync.aligned.m8n8.x4.shared.b16 {%0,%1,%2,%3}, [%4];"
        : "=r"(r[0]), "=r"(r[1]), "=r"(r[2]), "=r"(r[3]) : "r"(addr));
}
__device__ __forceinline__ void mma16816(float* d, const unsigned* a,
                                         unsigned b0, unsigned b1) {
    asm volatile(
        "mma.sync.aligned.m16n8k16.row.col.f32.bf16.bf16.f32 "
        "{%0,%1,%2,%3}, {%4,%5,%6,%7}, {%8,%9}, {%0,%1,%2,%3};"
        : "+f"(d[0]), "+f"(d[1]), "+f"(d[2]), "+f"(d[3])
        : "r"(a[0]), "r"(a[1]), "r"(a[2]), "r"(a[3]), "r"(b0), "r"(b1));
}

#define BKC 32   // bf16 elements per k-chunk

// ---------------------------------------------------------------------------
// D[M,N] = alpha * A3[M,K'] . B3[N,K']^T + bias   (both operands K-major)
// ---------------------------------------------------------------------------
__global__ void __launch_bounds__(256, 2)
hmma_gemm(const __nv_bfloat16* __restrict__ A, const __nv_bfloat16* __restrict__ B,
          float* __restrict__ Cout,
          int lda, int ldb, int ldc,
          long long sA, long long sB, long long sC,
          float alpha, const float* __restrict__ bias,
          int causal_skip, int klimit, int K3)
{
    const int row0 = blockIdx.y * 128;
    const int col0 = blockIdx.x * 128;
    if (causal_skip && col0 > row0) return;              // strictly-upper tiles
    const int kend = klimit ? min(K3, 3 * (row0 + 128)) : K3;
    const int nch = kend / BKC;

    A += (long long)blockIdx.z * sA + (long long)row0 * lda;
    B += (long long)blockIdx.z * sB + (long long)col0 * ldb;
    Cout += (long long)blockIdx.z * sC;

    __shared__ alignas(128) unsigned char smem[32768];   // 2 stages x (A 8K + B 8K)
    const unsigned sb = (unsigned)__cvta_generic_to_shared(smem);

    const int tid = threadIdx.x;
    const int lane = tid & 31;
    const int wid = tid >> 5;
    const int wm = wid >> 2;          // 0..1 -> 64-row half
    const int wn = wid & 3;           // 0..3 -> 32-col quarter

    float acc[4][4][4];
    #pragma unroll
    for (int i = 0; i < 4; i++)
        #pragma unroll
        for (int j = 0; j < 4; j++)
            #pragma unroll
            for (int k = 0; k < 4; k++) acc[i][j][k] = 0.f;

    auto load_tile = [&](int st, int kc) {
        const unsigned sA_ = sb + st * 16384;
        const unsigned sB_ = sA_ + 8192;
        #pragma unroll
        for (int p = 0; p < 2; p++) {
            const int id = tid + p * 256;
            const int r = id >> 2, c = id & 3;
            cp_async16(sA_ + SWOFF(r, c), A + (long long)r * lda + kc + c * 8);
            cp_async16(sB_ + SWOFF(r, c), B + (long long)r * ldb + kc + c * 8);
        }
        asm volatile("cp.async.commit_group;" ::: "memory");
    };

    auto compute = [&](int st) {
        const unsigned sA_ = sb + st * 16384;
        const unsigned sB_ = sA_ + 8192;
        #pragma unroll
        for (int ks = 0; ks < 2; ks++) {
            const int ch = ks * 2 + (lane >> 4);
            unsigned bfr[2][4];
            #pragma unroll
            for (int nh = 0; nh < 2; nh++) {
                const int nr = wn * 32 + nh * 16 + (lane & 15);
                ldm4(bfr[nh], sB_ + SWOFF(nr, ch));
            }
            #pragma unroll
            for (int mb = 0; mb < 4; mb++) {
                const int mr = wm * 64 + mb * 16 + (lane & 15);
                unsigned afr[4];
                ldm4(afr, sA_ + SWOFF(mr, ch));
                #pragma unroll
                for (int nb = 0; nb < 4; nb++)
                    mma16816(acc[mb][nb], afr,
                             bfr[nb >> 1][nb & 1], bfr[nb >> 1][(nb & 1) + 2]);
            }
        }
    };

    load_tile(0, 0);
    for (int i = 0; i < nch; i++) {
        if (i + 1 < nch) {
            load_tile((i + 1) & 1, (i + 1) * BKC);
            asm volatile("cp.async.wait_group 1;" ::: "memory");
        } else {
            asm volatile("cp.async.wait_group 0;" ::: "memory");
        }
        __syncthreads();
        compute(i & 1);
        __syncthreads();
    }

    // epilogue: c-frag rows g/g+8, col pairs 2*(lane&3)
    #pragma unroll
    for (int mb = 0; mb < 4; mb++) {
        #pragma unroll
        for (int half = 0; half < 2; half++) {
            const int r = row0 + wm * 64 + mb * 16 + (lane >> 2) + half * 8;
            float* cp = Cout + (long long)r * ldc + col0 + wn * 32 + 2 * (lane & 3);
            #pragma unroll
            for (int nb = 0; nb < 4; nb++) {
                float2 v;
                v.x = acc[mb][nb][half * 2 + 0] * alpha;
                v.y = acc[mb][nb][half * 2 + 1] * alpha;
                if (bias) {
                    const float* bp = bias + col0 + wn * 32 + nb * 8 + 2 * (lane & 3);
                    v.x += bp[0]; v.y += bp[1];
                }
                *(float2*)(cp + nb * 8) = v;
            }
        }
    }
}

// ---------------------------------------------------------------------------
// fp32 -> 3-term interleaved bf16 split at k' = 3k+{0,1,2}
//   ATYPE=1: (hi, lo, hi)    ATYPE=0 (B operand): (hi, hi, lo)
// ---------------------------------------------------------------------------
template <int ATYPE>
__global__ void split3_kernel(const float* __restrict__ in,
                              __nv_bfloat16* __restrict__ out,
                              int R, int Cin, int ld)
{
    const int c8n = Cin >> 3;
    long long idx = (long long)blockIdx.x * blockDim.x + threadIdx.x;
    if (idx >= (long long)R * c8n) return;
    const int r = (int)(idx / c8n);
    const int c = (int)(idx - (long long)r * c8n) * 8;

    const float4 v0 = *(const float4*)(in + (long long)r * ld + c);
    const float4 v1 = *(const float4*)(in + (long long)r * ld + c + 4);
    float f[8] = {v0.x, v0.y, v0.z, v0.w, v1.x, v1.y, v1.z, v1.w};

    unsigned short s[24];
    #pragma unroll
    for (int j = 0; j < 8; j++) {
        __nv_bfloat16 h = __float2bfloat16(f[j]);
        __nv_bfloat16 l = __float2bfloat16(f[j] - __bfloat162float(h));
        unsigned short hu = __bfloat16_as_ushort(h);
        unsigned short lu = __bfloat16_as_ushort(l);
        if (ATYPE) { s[3*j] = hu; s[3*j+1] = lu; s[3*j+2] = hu; }
        else       { s[3*j] = hu; s[3*j+1] = hu; s[3*j+2] = lu; }
    }
    __nv_bfloat16* op = out + (long long)r * (3 * Cin) + 3 * c;  // 48B aligned
    *(uint4*)(op)      = *(uint4*)(s);
    *(uint4*)(op + 8)  = *(uint4*)(s + 8);
    *(uint4*)(op + 16) = *(uint4*)(s + 16);
}

// V[s,c] (inside qkv, stride 3C) -> vt3[b][c][3s+{0,1,2}] = (hi,hi,lo)
__global__ void transpose_split3_kernel(const float* __restrict__ qkv,
                                        __nv_bfloat16* __restrict__ vt3)
{
    __shared__ float tile[32][33];
    const int b = blockIdx.z;
    const int s0 = blockIdx.x * 32, c0 = blockIdx.y * 32;
    const int tx = threadIdx.x, ty = threadIdx.y;
    tile[ty][tx] = qkv[((long long)(b * 2048 + s0 + ty)) * 3072 + 2048 + c0 + tx];
    __syncthreads();
    const float v = tile[tx][ty];
    __nv_bfloat16 h = __float2bfloat16(v);
    __nv_bfloat16 l = __float2bfloat16(v - __bfloat162float(h));
    __nv_bfloat16* op = vt3 + ((long long)(b * 1024 + c0 + ty)) * 6144 + 3 * (s0 + tx);
    op[0] = h; op[1] = h; op[2] = l;
}

// ---------------------------------------------------------------------------
// in-place causal softmax (zeros masked tail so att@V can read full tiles)
// ---------------------------------------------------------------------------
__global__ void softmax_kernel(float* __restrict__ att, int Tn)
{
    const int row = blockIdx.x;
    const int t = row % Tn;
    float* p = att + (long long)row * Tn;
    const int tid = threadIdx.x;
    const int len = t + 1;

    __shared__ float red[256];

    float m = -1e30f;
    for (int s = tid; s < len; s += 256) m = fmaxf(m, p[s]);
    red[tid] = m; __syncthreads();
    for (int off = 128; off > 0; off >>= 1) {
        if (tid < off) red[tid] = fmaxf(red[tid], red[tid + off]);
        __syncthreads();
    }
    m = red[0]; __syncthreads();

    float sum = 0.f;
    for (int s = tid; s < len; s += 256) {
        float e = __expf(p[s] - m);
        p[s] = e;
        sum += e;
    }
    red[tid] = sum; __syncthreads();
    for (int off = 128; off > 0; off >>= 1) {
        if (tid < off) red[tid] += red[tid + off];
        __syncthreads();
    }
    const float inv = 1.f / red[0];

    for (int s = tid; s < len; s += 256) p[s] *= inv;
    for (int s = len + tid; s < Tn; s += 256) p[s] = 0.f;
}

// ---------------------------------------------------------------------------
extern "C" void kernel_launch(void* const* d_in, const int* in_sizes, int n_in,
                              void* d_out, int out_size)
{
    const float* x      = (const float*)d_in[0];
    const float* w_qkv  = (const float*)d_in[1];
    const float* b_qkv  = (const float*)d_in[2];
    const float* w_proj = (const float*)d_in[3];
    const float* b_proj = (const float*)d_in[4];
    float* out = (float*)d_out;

    float *qkv, *att, *o;
    __nv_bfloat16 *x3, *wqkv3, *wproj3, *q3, *k3, *vt3, *att3, *o3;
    cudaGetSymbolAddress((void**)&qkv, g_qkv);
    cudaGetSymbolAddress((void**)&att, g_att);
    cudaGetSymbolAddress((void**)&o,   g_o);
    cudaGetSymbolAddress((void**)&x3,    g_x3);
    cudaGetSymbolAddress((void**)&wqkv3, g_wqkv3);
    cudaGetSymbolAddress((void**)&wproj3,g_wproj3);
    cudaGetSymbolAddress((void**)&q3,    g_q3);
    cudaGetSymbolAddress((void**)&k3,    g_k3);
    cudaGetSymbolAddress((void**)&vt3,   g_vt3);
    cudaGetSymbolAddress((void**)&att3,  g_att3);
    cudaGetSymbolAddress((void**)&o3,    g_o3);

    const float inv_sqrt_c = 0.03125f;

    // split inputs
    split3_kernel<1><<<(M * (C / 8) + 255) / 256, 256>>>(x, x3, M, C, C);
    split3_kernel<0><<<(3 * C * (C / 8) + 255) / 256, 256>>>(w_qkv, wqkv3, 3 * C, C, C);
    split3_kernel<0><<<(C * (C / 8) + 255) / 256, 256>>>(w_proj, wproj3, C, C, C);

    // 1) qkv = x @ w_qkv^T + b_qkv   [8192, 3072]
    hmma_gemm<<<dim3(3 * C / 128, M / 128, 1), 256>>>(
        x3, wqkv3, qkv, K3C, K3C, 3 * C, 0, 0, 0,
        1.f, b_qkv, 0, 0, K3C);

    // split q (A-type), k (B-type); transpose-split v (B-type)
    split3_kernel<1><<<(M * (C / 8) + 255) / 256, 256>>>(qkv,     q3, M, C, 3 * C);
    split3_kernel<0><<<(M * (C / 8) + 255) / 256, 256>>>(qkv + C, k3, M, C, 3 * C);
    transpose_split3_kernel<<<dim3(T / 32, C / 32, Bb), dim3(32, 32)>>>(qkv, vt3);

    // 2) scores = (q @ k^T) / sqrt(C), causal tile-skip
    hmma_gemm<<<dim3(T / 128, T / 128, Bb), 256>>>(
        q3, k3, att, K3C, K3C, T,
        (long long)T * K3C, (long long)T * K3C, (long long)T * T,
        inv_sqrt_c, nullptr, 1, 0, K3C);

    // 3) softmax
    softmax_kernel<<<M, 256>>>(att, T);

    // split att (A-type)
    split3_kernel<1><<<(M * (T / 8) + 255) / 256, 256>>>(att, att3, M, T, T);

    // 4) o = att @ V  (k-limited by causality)
    hmma_gemm<<<dim3(C / 128, T / 128, Bb), 256>>>(
        att3, vt3, o, K3T, K3T, C,
        (long long)T * K3T, (long long)C * K3T, (long long)T * C,
        1.f, nullptr, 0, 1, K3T);

    // split o (A-type)
    split3_kernel<1><<<(M * (C / 8) + 255) / 256, 256>>>(o, o3, M, C, C);

    // 5) out = o @ w_proj^T + b_proj
    hmma_gemm<<<dim3(C / 128, M / 128, 1), 256>>>(
        o3, wproj3, out, K3C, K3C, C, 0, 0, 0,
        1.f, b_proj, 0, 0, K3C);
}

// round 5
// speedup vs baseline: 2.2368x; 1.0047x over previous
#include <cuda_runtime.h>
#include <cuda_bf16.h>
#include <math.h>

// ---------------------------------------------------------------------------
// Causal self-attention block via mma.sync (HMMA bf16) on sm_103.
// fp32 emulation by 3-term bf16 split along K (k' = 3k + {0,1,2}):
//   A3 = (Ah, Al, Ah),  B3 = (Bh, Bh, Bl)  -> drops only Al*Bl (~2^-18).
// R5: 3-stage cp.async pipeline w/ 1 sync per k-chunk; split passes fused
// into GEMM epilogues + softmax; polynomial exp (MUFU EX2 is 1/4-rate).
// ---------------------------------------------------------------------------

static const int Bb = 4, T = 2048, C = 1024;
static const int M = Bb * T;          // 8192
static const int K3C = 3 * C;         // 3072
static const int K3T = 3 * T;         // 6144

// fp32 intermediates
__device__ float g_att[(size_t)4 * 2048 * 2048];
__device__ float g_v  [(size_t)8192 * 1024];
// 3-split bf16 operands
__device__ __nv_bfloat16 g_x3    [(size_t)8192 * 3072];
__device__ __nv_bfloat16 g_wqkv3 [(size_t)3072 * 3072];
__device__ __nv_bfloat16 g_wproj3[(size_t)1024 * 3072];
__device__ __nv_bfloat16 g_q3    [(size_t)8192 * 3072];
__device__ __nv_bfloat16 g_k3    [(size_t)8192 * 3072];
__device__ __nv_bfloat16 g_vt3   [(size_t)4 * 1024 * 6144];
__device__ __nv_bfloat16 g_att3  [(size_t)8192 * 6144];
__device__ __nv_bfloat16 g_o3    [(size_t)8192 * 3072];

// 16B-chunk XOR swizzle: row r (64B rows), chunk c in 0..3.
#define SWOFF(r, c) ((unsigned)((r) * 64 + ((((c) ^ (((r) >> 1) & 3)) & 3) << 4)))

__device__ __forceinline__ void cp_async16(unsigned s, const void* g) {
    asm volatile("cp.async.cg.shared.global [%0], [%1], 16;"
        :: "r"(s), "l"(__cvta_generic_to_global(g)) : "memory");
}
__device__ __forceinline__ void ldm4(unsigned* r, unsigned addr) {
    asm volatile("ldmatrix.sync.aligned.m8n8.x4.shared.b16 {%0,%1,%2,%3}, [%4];"
        : "=r"(r[0]), "=r"(r[1]), "=r"(r[2]), "=r"(r[3]) : "r"(addr));
}
__device__ __forceinline__ void mma16816(float* d, const unsigned* a,
                                         unsigned b0, unsigned b1) {
    asm volatile(
        "mma.sync.aligned.m16n8k16.row.col.f32.bf16.bf16.f32 "
        "{%0,%1,%2,%3}, {%4,%5,%6,%7}, {%8,%9}, {%0,%1,%2,%3};"
        : "+f"(d[0]), "+f"(d[1]), "+f"(d[2]), "+f"(d[3])
        : "r"(a[0]), "r"(a[1]), "r"(a[2]), "r"(a[3]), "r"(b0), "r"(b1));
}

// pack (vx, vy) as 3-term split -> 3 u32 stores (12B)
// satype=1: (h,l,h)(h2,l2,h2)   satype=0: (h,h,l)(h2,h2,l2)
__device__ __forceinline__ void store3(__nv_bfloat16* p, float vx, float vy,
                                       int satype) {
    __nv_bfloat16 hx = __float2bfloat16(vx);
    __nv_bfloat16 lx = __float2bfloat16(vx - __bfloat162float(hx));
    __nv_bfloat16 hy = __float2bfloat16(vy);
    __nv_bfloat16 ly = __float2bfloat16(vy - __bfloat162float(hy));
    unsigned hxu = __bfloat16_as_ushort(hx), lxu = __bfloat16_as_ushort(lx);
    unsigned hyu = __bfloat16_as_ushort(hy), lyu = __bfloat16_as_ushort(ly);
    unsigned u0, u1, u2;
    if (satype) { u0 = hxu | (lxu << 16); u1 = hxu | (hyu << 16); u2 = lyu | (hyu << 16); }
    else        { u0 = hxu | (hxu << 16); u1 = lxu | (hyu << 16); u2 = hyu | (lyu << 16); }
    unsigned* up = (unsigned*)p;
    up[0] = u0; up[1] = u1; up[2] = u2;
}

#define BKC 32        // bf16 elements per k-chunk
#define NSTG 3        // cp.async pipeline stages

// ---------------------------------------------------------------------------
// D[M,N] = alpha * A3[M,K'] . B3[N,K']^T (+ bias)   (both operands K-major)
// emode 0: fp32 out (Cf, ldcf)          [scores, proj]
// emode 1: A-split bf16 out (C3a, ldc3) [att@V -> o3]
// emode 2: qkv triple: col<1024 -> q3 (A-split), <2048 -> k3 (B-split),
//          else fp32 -> Cv (ld 1024). bias indexed by absolute col.
// ---------------------------------------------------------------------------
__global__ void __launch_bounds__(256, 2)
hmma_gemm(const __nv_bfloat16* __restrict__ A, const __nv_bfloat16* __restrict__ B,
          float* __restrict__ Cf, __nv_bfloat16* __restrict__ C3a,
          __nv_bfloat16* __restrict__ C3b, float* __restrict__ Cv,
          int lda, int ldb, int ldcf, int ldc3,
          long long sA, long long sB, long long sC,
          float alpha, const float* __restrict__ bias,
          int causal_skip, int klimit, int K3, int emode)
{
    const int row0 = blockIdx.y * 128;
    const int col0 = blockIdx.x * 128;
    if (causal_skip && col0 > row0) return;              // strictly-upper tiles
    const int kend = klimit ? min(K3, 3 * (row0 + 128)) : K3;
    const int nch = kend / BKC;

    A += (long long)blockIdx.z * sA + (long long)row0 * lda;
    B += (long long)blockIdx.z * sB + (long long)col0 * ldb;

    __shared__ alignas(128) unsigned char smem[NSTG * 16384];
    const unsigned sb = (unsigned)__cvta_generic_to_shared(smem);

    const int tid = threadIdx.x;
    const int lane = tid & 31;
    const int wid = tid >> 5;
    const int wm = wid >> 2;          // 0..1 -> 64-row half
    const int wn = wid & 3;           // 0..3 -> 32-col quarter

    float acc[4][4][4];
    #pragma unroll
    for (int i = 0; i < 4; i++)
        #pragma unroll
        for (int j = 0; j < 4; j++)
            #pragma unroll
            for (int k = 0; k < 4; k++) acc[i][j][k] = 0.f;

    auto load_tile = [&](int st, int kc) {
        const unsigned sA_ = sb + st * 16384;
        const unsigned sB_ = sA_ + 8192;
        #pragma unroll
        for (int p = 0; p < 2; p++) {
            const int id = tid + p * 256;
            const int r = id >> 2, c = id & 3;
            cp_async16(sA_ + SWOFF(r, c), A + (long long)r * lda + kc + c * 8);
            cp_async16(sB_ + SWOFF(r, c), B + (long long)r * ldb + kc + c * 8);
        }
        asm volatile("cp.async.commit_group;" ::: "memory");
    };

    auto compute = [&](int st) {
        const unsigned sA_ = sb + st * 16384;
        const unsigned sB_ = sA_ + 8192;
        #pragma unroll
        for (int ks = 0; ks < 2; ks++) {
            const int ch = ks * 2 + (lane >> 4);
            unsigned bfr[2][4];
            #pragma unroll
            for (int nh = 0; nh < 2; nh++) {
                const int nr = wn * 32 + nh * 16 + (lane & 15);
                ldm4(bfr[nh], sB_ + SWOFF(nr, ch));
            }
            #pragma unroll
            for (int mb = 0; mb < 4; mb++) {
                const int mr = wm * 64 + mb * 16 + (lane & 15);
                unsigned afr[4];
                ldm4(afr, sA_ + SWOFF(mr, ch));
                #pragma unroll
                for (int nb = 0; nb < 4; nb++)
                    mma16816(acc[mb][nb], afr,
                             bfr[nb >> 1][nb & 1], bfr[nb >> 1][(nb & 1) + 2]);
            }
        }
    };

    // prologue: stages 0, 1
    load_tile(0, 0);
    load_tile(1, BKC);
    for (int i = 0; i < nch; i++) {
        if (i < nch - 1) asm volatile("cp.async.wait_group 1;" ::: "memory");
        else             asm volatile("cp.async.wait_group 0;" ::: "memory");
        __syncthreads();
        const int nx = i + NSTG - 1;
        if (nx < nch) load_tile(nx % NSTG, nx * BKC);
        compute(i % NSTG);
    }

    // ----- epilogue -----
    // resolve destination
    __nv_bfloat16* d3 = 0;
    int satype = 1, colr = col0;
    float* df = 0;
    int ldf = ldcf;
    if (emode == 0) {
        df = Cf + (long long)blockIdx.z * sC;
    } else if (emode == 1) {
        d3 = C3a + (long long)blockIdx.z * sC;
    } else {                                  // qkv triple
        if (col0 < 1024)      { d3 = C3a; satype = 1; colr = col0; }
        else if (col0 < 2048) { d3 = C3b; satype = 0; colr = col0 - 1024; }
        else                  { df = Cv; ldf = 1024; colr = col0 - 2048; }
    }

    const int cbase = wn * 32 + 2 * (lane & 3);
    #pragma unroll
    for (int mb = 0; mb < 4; mb++) {
        #pragma unroll
        for (int half = 0; half < 2; half++) {
            const int r = row0 + wm * 64 + mb * 16 + (lane >> 2) + half * 8;
            #pragma unroll
            for (int nb = 0; nb < 4; nb++) {
                const int cr = colr + cbase + nb * 8;    // region-relative (even)
                const int ca = col0 + cbase + nb * 8;    // absolute (bias)
                float vx = acc[mb][nb][half * 2 + 0] * alpha;
                float vy = acc[mb][nb][half * 2 + 1] * alpha;
                if (bias) { vx += bias[ca]; vy += bias[ca + 1]; }
                if (d3) store3(d3 + (long long)r * ldc3 + 3 * cr, vx, vy, satype);
                else    *(float2*)(df + (long long)r * ldf + cr) = make_float2(vx, vy);
            }
        }
    }
}

// ---------------------------------------------------------------------------
// fp32 -> 3-term interleaved bf16 split (standalone; inputs only)
// ---------------------------------------------------------------------------
template <int ATYPE>
__global__ void split3_kernel(const float* __restrict__ in,
                              __nv_bfloat16* __restrict__ out,
                              int R, int Cin, int ld)
{
    const int c8n = Cin >> 3;
    long long idx = (long long)blockIdx.x * blockDim.x + threadIdx.x;
    if (idx >= (long long)R * c8n) return;
    const int r = (int)(idx / c8n);
    const int c = (int)(idx - (long long)r * c8n) * 8;

    const float4 v0 = *(const float4*)(in + (long long)r * ld + c);
    const float4 v1 = *(const float4*)(in + (long long)r * ld + c + 4);
    float f[8] = {v0.x, v0.y, v0.z, v0.w, v1.x, v1.y, v1.z, v1.w};

    alignas(16) unsigned short s[24];
    #pragma unroll
    for (int j = 0; j < 8; j++) {
        __nv_bfloat16 h = __float2bfloat16(f[j]);
        __nv_bfloat16 l = __float2bfloat16(f[j] - __bfloat162float(h));
        unsigned short hu = __bfloat16_as_ushort(h);
        unsigned short lu = __bfloat16_as_ushort(l);
        if (ATYPE) { s[3*j] = hu; s[3*j+1] = lu; s[3*j+2] = hu; }
        else       { s[3*j] = hu; s[3*j+1] = hu; s[3*j+2] = lu; }
    }
    __nv_bfloat16* op = out + (long long)r * (3 * Cin) + 3 * c;
    *(uint4*)(op)      = *(uint4*)(s);
    *(uint4*)(op + 8)  = *(uint4*)(s + 8);
    *(uint4*)(op + 16) = *(uint4*)(s + 16);
}

// V[s,c] fp32 [8192,1024] -> vt3[b][c][3s+{0,1,2}] = (hi,hi,lo)
__global__ void transpose_split3_kernel(const float* __restrict__ v,
                                        __nv_bfloat16* __restrict__ vt3)
{
    __shared__ float tile[32][33];
    const int b = blockIdx.z;
    const int s0 = blockIdx.x * 32, c0 = blockIdx.y * 32;
    const int tx = threadIdx.x, ty = threadIdx.y;
    tile[ty][tx] = v[((long long)(b * 2048 + s0 + ty)) * 1024 + c0 + tx];
    __syncthreads();
    const float val = tile[tx][ty];
    __nv_bfloat16 h = __float2bfloat16(val);
    __nv_bfloat16 l = __float2bfloat16(val - __bfloat162float(h));
    __nv_bfloat16* op = vt3 + ((long long)(b * 1024 + c0 + ty)) * 6144 + 3 * (s0 + tx);
    op[0] = h; op[1] = h; op[2] = l;
}

// ---------------------------------------------------------------------------
// FMA-pipe exp for x <= 0 (MUFU EX2 is quarter-rate on B300).
// exp(x) = 2^(x*log2e); degree-6 Taylor of 2^f on [0,1): rel err ~1e-5.
// ---------------------------------------------------------------------------
__device__ __forceinline__ float fexp(float x) {
    float y = x * 1.4426950408889634f;
    float n = floorf(y);
    float f = y - n;
    float p = 0.000154035304f;
    p = fmaf(p, f, 0.00133335581f);
    p = fmaf(p, f, 0.00961812910f);
    p = fmaf(p, f, 0.0555041087f);
    p = fmaf(p, f, 0.240226507f);
    p = fmaf(p, f, 0.693147180f);
    p = fmaf(p, f, 1.0f);
    int ni = (int)n;
    if (ni < -126) return 0.f;
    return p * __int_as_float((ni + 127) << 23);
}

// ---------------------------------------------------------------------------
// causal softmax: reads fp32 scores, writes A-split bf16 att3 (zeros tail)
// ---------------------------------------------------------------------------
__global__ void softmax_split_kernel(const float* __restrict__ att,
                                     __nv_bfloat16* __restrict__ att3, int Tn)
{
    __shared__ float buf[2048];
    __shared__ float red[256];
    const int row = blockIdx.x;
    const int t = row % Tn;
    const float* p = att + (long long)row * Tn;
    const int tid = threadIdx.x;
    const int len = t + 1;

    float m = -1e30f;
    for (int s = tid; s < len; s += 256) { float v = p[s]; buf[s] = v; m = fmaxf(m, v); }
    red[tid] = m; __syncthreads();
    for (int off = 128; off > 0; off >>= 1) {
        if (tid < off) red[tid] = fmaxf(red[tid], red[tid + off]);
        __syncthreads();
    }
    m = red[0]; __syncthreads();

    float sum = 0.f;
    for (int s = tid; s < len; s += 256) {
        float e = fexp(buf[s] - m);
        buf[s] = e;
        sum += e;
    }
    red[tid] = sum; __syncthreads();
    for (int off = 128; off > 0; off >>= 1) {
        if (tid < off) red[tid] += red[tid + off];
        __syncthreads();
    }
    const float inv = 1.f / red[0];
    __syncthreads();

    // write 8 cols per thread -> 24 bf16 = 48B = 3x uint4 (16B aligned)
    __nv_bfloat16* out = att3 + (long long)row * (3 * Tn);
    const int s8 = tid * 8;                 // 256*8 == Tn: one pass
    alignas(16) unsigned short sh[24];
    #pragma unroll
    for (int j = 0; j < 8; j++) {
        const int s = s8 + j;
        const float e = (s < len) ? buf[s] * inv : 0.f;
        __nv_bfloat16 h = __float2bfloat16(e);
        __nv_bfloat16 l = __float2bfloat16(e - __bfloat162float(h));
        sh[3*j] = __bfloat16_as_ushort(h);
        sh[3*j+1] = __bfloat16_as_ushort(l);
        sh[3*j+2] = __bfloat16_as_ushort(h);
    }
    __nv_bfloat16* op = out + 3 * s8;
    *(uint4*)(op)      = *(uint4*)(sh);
    *(uint4*)(op + 8)  = *(uint4*)(sh + 8);
    *(uint4*)(op + 16) = *(uint4*)(sh + 16);
}

// ---------------------------------------------------------------------------
extern "C" void kernel_launch(void* const* d_in, const int* in_sizes, int n_in,
                              void* d_out, int out_size)
{
    const float* x      = (const float*)d_in[0];
    const float* w_qkv  = (const float*)d_in[1];
    const float* b_qkv  = (const float*)d_in[2];
    const float* w_proj = (const float*)d_in[3];
    const float* b_proj = (const float*)d_in[4];
    float* out = (float*)d_out;

    float *att, *v;
    __nv_bfloat16 *x3, *wqkv3, *wproj3, *q3, *k3, *vt3, *att3, *o3;
    cudaGetSymbolAddress((void**)&att, g_att);
    cudaGetSymbolAddress((void**)&v,   g_v);
    cudaGetSymbolAddress((void**)&x3,    g_x3);
    cudaGetSymbolAddress((void**)&wqkv3, g_wqkv3);
    cudaGetSymbolAddress((void**)&wproj3,g_wproj3);
    cudaGetSymbolAddress((void**)&q3,    g_q3);
    cudaGetSymbolAddress((void**)&k3,    g_k3);
    cudaGetSymbolAddress((void**)&vt3,   g_vt3);
    cudaGetSymbolAddress((void**)&att3,  g_att3);
    cudaGetSymbolAddress((void**)&o3,    g_o3);

    const float inv_sqrt_c = 0.03125f;

    // split the raw inputs
    split3_kernel<1><<<(M * (C / 8) + 255) / 256, 256>>>(x, x3, M, C, C);
    split3_kernel<0><<<(3 * C * (C / 8) + 255) / 256, 256>>>(w_qkv, wqkv3, 3 * C, C, C);
    split3_kernel<0><<<(C * (C / 8) + 255) / 256, 256>>>(w_proj, wproj3, C, C, C);

    // 1) qkv GEMM, fused epilogue -> q3 (A-split) / k3 (B-split) / v (fp32)
    hmma_gemm<<<dim3(3 * C / 128, M / 128, 1), 256>>>(
        x3, wqkv3, nullptr, q3, k3, v,
        K3C, K3C, 0, K3C, 0, 0, 0,
        1.f, b_qkv, 0, 0, K3C, 2);

    // transpose-split v -> vt3 (B-type)
    transpose_split3_kernel<<<dim3(T / 32, C / 32, Bb), dim3(32, 32)>>>(v, vt3);

    // 2) scores = (q @ k^T) / sqrt(C), causal tile-skip, fp32 out
    hmma_gemm<<<dim3(T / 128, T / 128, Bb), 256>>>(
        q3, k3, att, nullptr, nullptr, nullptr,
        K3C, K3C, T, 0,
        (long long)T * K3C, (long long)T * K3C, (long long)T * T,
        inv_sqrt_c, nullptr, 1, 0, K3C, 0);

    // 3) softmax fused with A-split -> att3 (zeros masked tail)
    softmax_split_kernel<<<M, 256>>>(att, att3, T);

    // 4) o = att @ V  (k-limited), fused epilogue -> o3 (A-split)
    hmma_gemm<<<dim3(C / 128, T / 128, Bb), 256>>>(
        att3, vt3, nullptr, o3, nullptr, nullptr,
        K3T, K3T, 0, K3C,
        (long long)T * K3T, (long long)C * K3T, (long long)T * K3C,
        1.f, nullptr, 0, 1, K3T, 1);

    // 5) out = o @ w_proj^T + b_proj   (fp32 out)
    hmma_gemm<<<dim3(C / 128, M / 128, 1), 256>>>(
        o3, wproj3, out, nullptr, nullptr, nullptr,
        K3C, K3C, C, 0, 0, 0, 0,
        1.f, b_proj, 0, 0, K3C, 0);
}

// round 6
// speedup vs baseline: 2.2787x; 1.0187x over previous
#include <cuda_runtime.h>
#include <cuda_bf16.h>
#include <math.h>

// ---------------------------------------------------------------------------
// Causal self-attention block via mma.sync (HMMA bf16) on sm_103.
// fp32 emulation by 3-term bf16 split along K (k' = 3k + {0,1,2}):
//   A3 = (Ah, Al, Ah),  B3 = (Bh, Bh, Bl)  -> drops only Al*Bl (~2^-18).
// R6: 4 warps x 64x64 warp tiles (MMA:ldmatrix 4:1), 128-thread CTAs with
// 2 CTAs/SM so barriers in one CTA overlap MMA in the other.
// ---------------------------------------------------------------------------

static const int Bb = 4, T = 2048, C = 1024;
static const int M = Bb * T;          // 8192
static const int K3C = 3 * C;         // 3072
static const int K3T = 3 * T;         // 6144

// fp32 intermediates
__device__ float g_att[(size_t)4 * 2048 * 2048];
__device__ float g_v  [(size_t)8192 * 1024];
// 3-split bf16 operands
__device__ __nv_bfloat16 g_x3    [(size_t)8192 * 3072];
__device__ __nv_bfloat16 g_wqkv3 [(size_t)3072 * 3072];
__device__ __nv_bfloat16 g_wproj3[(size_t)1024 * 3072];
__device__ __nv_bfloat16 g_q3    [(size_t)8192 * 3072];
__device__ __nv_bfloat16 g_k3    [(size_t)8192 * 3072];
__device__ __nv_bfloat16 g_vt3   [(size_t)4 * 1024 * 6144];
__device__ __nv_bfloat16 g_att3  [(size_t)8192 * 6144];
__device__ __nv_bfloat16 g_o3    [(size_t)8192 * 3072];

// 16B-chunk XOR swizzle: row r (64B rows), chunk c in 0..3.
#define SWOFF(r, c) ((unsigned)((r) * 64 + ((((c) ^ (((r) >> 1) & 3)) & 3) << 4)))

__device__ __forceinline__ void cp_async16(unsigned s, const void* g) {
    asm volatile("cp.async.cg.shared.global [%0], [%1], 16;"
        :: "r"(s), "l"(__cvta_generic_to_global(g)) : "memory");
}
__device__ __forceinline__ void ldm4(unsigned* r, unsigned addr) {
    asm volatile("ldmatrix.sync.aligned.m8n8.x4.shared.b16 {%0,%1,%2,%3}, [%4];"
        : "=r"(r[0]), "=r"(r[1]), "=r"(r[2]), "=r"(r[3]) : "r"(addr));
}
__device__ __forceinline__ void mma16816(float* d, const unsigned* a,
                                         unsigned b0, unsigned b1) {
    asm volatile(
        "mma.sync.aligned.m16n8k16.row.col.f32.bf16.bf16.f32 "
        "{%0,%1,%2,%3}, {%4,%5,%6,%7}, {%8,%9}, {%0,%1,%2,%3};"
        : "+f"(d[0]), "+f"(d[1]), "+f"(d[2]), "+f"(d[3])
        : "r"(a[0]), "r"(a[1]), "r"(a[2]), "r"(a[3]), "r"(b0), "r"(b1));
}

// pack (vx, vy) as 3-term split -> 3 u32 stores (12B)
// satype=1: (h,l,h)(h2,l2,h2)   satype=0: (h,h,l)(h2,h2,l2)
__device__ __forceinline__ void store3(__nv_bfloat16* p, float vx, float vy,
                                       int satype) {
    __nv_bfloat16 hx = __float2bfloat16(vx);
    __nv_bfloat16 lx = __float2bfloat16(vx - __bfloat162float(hx));
    __nv_bfloat16 hy = __float2bfloat16(vy);
    __nv_bfloat16 ly = __float2bfloat16(vy - __bfloat162float(hy));
    unsigned hxu = __bfloat16_as_ushort(hx), lxu = __bfloat16_as_ushort(lx);
    unsigned hyu = __bfloat16_as_ushort(hy), lyu = __bfloat16_as_ushort(ly);
    unsigned u0, u1, u2;
    if (satype) { u0 = hxu | (lxu << 16); u1 = hxu | (hyu << 16); u2 = lyu | (hyu << 16); }
    else        { u0 = hxu | (hxu << 16); u1 = lxu | (hyu << 16); u2 = hyu | (lyu << 16); }
    unsigned* up = (unsigned*)p;
    up[0] = u0; up[1] = u1; up[2] = u2;
}

#define BKC 32        // bf16 elements per k-chunk
#define NSTG 3        // cp.async pipeline stages

// ---------------------------------------------------------------------------
// D[M,N] = alpha * A3[M,K'] . B3[N,K']^T (+ bias)   (both operands K-major)
// 128 threads, 4 warps, 64x64 warp tiles over a 128x128 CTA tile.
// emode 0: fp32 out (Cf, ldcf)          [scores, proj]
// emode 1: A-split bf16 out (C3a, ldc3) [att@V -> o3]
// emode 2: qkv triple: col<1024 -> q3 (A-split), <2048 -> k3 (B-split),
//          else fp32 -> Cv (ld 1024). bias indexed by absolute col.
// ---------------------------------------------------------------------------
__global__ void __launch_bounds__(128, 2)
hmma_gemm(const __nv_bfloat16* __restrict__ A, const __nv_bfloat16* __restrict__ B,
          float* __restrict__ Cf, __nv_bfloat16* __restrict__ C3a,
          __nv_bfloat16* __restrict__ C3b, float* __restrict__ Cv,
          int lda, int ldb, int ldcf, int ldc3,
          long long sA, long long sB, long long sC,
          float alpha, const float* __restrict__ bias,
          int causal_skip, int klimit, int K3, int emode)
{
    const int row0 = blockIdx.y * 128;
    const int col0 = blockIdx.x * 128;
    if (causal_skip && col0 > row0) return;              // strictly-upper tiles
    const int kend = klimit ? min(K3, 3 * (row0 + 128)) : K3;
    const int nch = kend / BKC;

    A += (long long)blockIdx.z * sA + (long long)row0 * lda;
    B += (long long)blockIdx.z * sB + (long long)col0 * ldb;

    __shared__ alignas(128) unsigned char smem[NSTG * 16384];
    const unsigned sb = (unsigned)__cvta_generic_to_shared(smem);

    const int tid = threadIdx.x;
    const int lane = tid & 31;
    const int wid = tid >> 5;          // 0..3
    const int wm = wid >> 1;           // 0..1 -> 64-row half
    const int wn = wid & 1;            // 0..1 -> 64-col half

    float acc[4][8][4];
    #pragma unroll
    for (int i = 0; i < 4; i++)
        #pragma unroll
        for (int j = 0; j < 8; j++)
            #pragma unroll
            for (int k = 0; k < 4; k++) acc[i][j][k] = 0.f;

    auto load_tile = [&](int st, int kc) {
        const unsigned sA_ = sb + st * 16384;
        const unsigned sB_ = sA_ + 8192;
        #pragma unroll
        for (int p = 0; p < 4; p++) {
            const int id = tid + p * 128;
            const int r = id >> 2, c = id & 3;
            cp_async16(sA_ + SWOFF(r, c), A + (long long)r * lda + kc + c * 8);
            cp_async16(sB_ + SWOFF(r, c), B + (long long)r * ldb + kc + c * 8);
        }
        asm volatile("cp.async.commit_group;" ::: "memory");
    };

    auto compute = [&](int st) {
        const unsigned sA_ = sb + st * 16384;
        const unsigned sB_ = sA_ + 8192;
        #pragma unroll
        for (int ks = 0; ks < 2; ks++) {
            const int ch = ks * 2 + (lane >> 4);
            unsigned bfr[4][4];
            #pragma unroll
            for (int nbb = 0; nbb < 4; nbb++) {
                const int nr = wn * 64 + nbb * 16 + (lane & 15);
                ldm4(bfr[nbb], sB_ + SWOFF(nr, ch));
            }
            #pragma unroll
            for (int mb = 0; mb < 4; mb++) {
                const int mr = wm * 64 + mb * 16 + (lane & 15);
                unsigned afr[4];
                ldm4(afr, sA_ + SWOFF(mr, ch));
                #pragma unroll
                for (int nbb = 0; nbb < 4; nbb++) {
                    mma16816(acc[mb][nbb * 2 + 0], afr, bfr[nbb][0], bfr[nbb][2]);
                    mma16816(acc[mb][nbb * 2 + 1], afr, bfr[nbb][1], bfr[nbb][3]);
                }
            }
        }
    };

    // prologue: stages 0, 1
    load_tile(0, 0);
    load_tile(1, BKC);
    for (int i = 0; i < nch; i++) {
        if (i < nch - 1) asm volatile("cp.async.wait_group 1;" ::: "memory");
        else             asm volatile("cp.async.wait_group 0;" ::: "memory");
        __syncthreads();
        const int nx = i + NSTG - 1;
        if (nx < nch) load_tile(nx % NSTG, nx * BKC);
        compute(i % NSTG);
    }

    // ----- epilogue -----
    __nv_bfloat16* d3 = 0;
    int satype = 1, colr = col0;
    float* df = 0;
    int ldf = ldcf;
    if (emode == 0) {
        df = Cf + (long long)blockIdx.z * sC;
    } else if (emode == 1) {
        d3 = C3a + (long long)blockIdx.z * sC;
    } else {                                  // qkv triple
        if (col0 < 1024)      { d3 = C3a; satype = 1; colr = col0; }
        else if (col0 < 2048) { d3 = C3b; satype = 0; colr = col0 - 1024; }
        else                  { df = Cv; ldf = 1024; colr = col0 - 2048; }
    }

    const int cbase = wn * 64 + 2 * (lane & 3);
    #pragma unroll
    for (int mb = 0; mb < 4; mb++) {
        #pragma unroll
        for (int half = 0; half < 2; half++) {
            const int r = row0 + wm * 64 + mb * 16 + (lane >> 2) + half * 8;
            #pragma unroll
            for (int nb = 0; nb < 8; nb++) {
                const int cr = colr + cbase + nb * 8;    // region-relative (even)
                const int ca = col0 + cbase + nb * 8;    // absolute (bias)
                float vx = acc[mb][nb][half * 2 + 0] * alpha;
                float vy = acc[mb][nb][half * 2 + 1] * alpha;
                if (bias) { vx += bias[ca]; vy += bias[ca + 1]; }
                if (d3) store3(d3 + (long long)r * ldc3 + 3 * cr, vx, vy, satype);
                else    *(float2*)(df + (long long)r * ldf + cr) = make_float2(vx, vy);
            }
        }
    }
}

// ---------------------------------------------------------------------------
// fp32 -> 3-term interleaved bf16 split (standalone; inputs only)
// ---------------------------------------------------------------------------
template <int ATYPE>
__global__ void split3_kernel(const float* __restrict__ in,
                              __nv_bfloat16* __restrict__ out,
                              int R, int Cin, int ld)
{
    const int c8n = Cin >> 3;
    long long idx = (long long)blockIdx.x * blockDim.x + threadIdx.x;
    if (idx >= (long long)R * c8n) return;
    const int r = (int)(idx / c8n);
    const int c = (int)(idx - (long long)r * c8n) * 8;

    const float4 v0 = *(const float4*)(in + (long long)r * ld + c);
    const float4 v1 = *(const float4*)(in + (long long)r * ld + c + 4);
    float f[8] = {v0.x, v0.y, v0.z, v0.w, v1.x, v1.y, v1.z, v1.w};

    alignas(16) unsigned short s[24];
    #pragma unroll
    for (int j = 0; j < 8; j++) {
        __nv_bfloat16 h = __float2bfloat16(f[j]);
        __nv_bfloat16 l = __float2bfloat16(f[j] - __bfloat162float(h));
        unsigned short hu = __bfloat16_as_ushort(h);
        unsigned short lu = __bfloat16_as_ushort(l);
        if (ATYPE) { s[3*j] = hu; s[3*j+1] = lu; s[3*j+2] = hu; }
        else       { s[3*j] = hu; s[3*j+1] = hu; s[3*j+2] = lu; }
    }
    __nv_bfloat16* op = out + (long long)r * (3 * Cin) + 3 * c;
    *(uint4*)(op)      = *(uint4*)(s);
    *(uint4*)(op + 8)  = *(uint4*)(s + 8);
    *(uint4*)(op + 16) = *(uint4*)(s + 16);
}

// V[s,c] fp32 [8192,1024] -> vt3[b][c][3s+{0,1,2}] = (hi,hi,lo)
__global__ void transpose_split3_kernel(const float* __restrict__ v,
                                        __nv_bfloat16* __restrict__ vt3)
{
    __shared__ float tile[32][33];
    const int b = blockIdx.z;
    const int s0 = blockIdx.x * 32, c0 = blockIdx.y * 32;
    const int tx = threadIdx.x, ty = threadIdx.y;
    tile[ty][tx] = v[((long long)(b * 2048 + s0 + ty)) * 1024 + c0 + tx];
    __syncthreads();
    const float val = tile[tx][ty];
    __nv_bfloat16 h = __float2bfloat16(val);
    __nv_bfloat16 l = __float2bfloat16(val - __bfloat162float(h));
    __nv_bfloat16* op = vt3 + ((long long)(b * 1024 + c0 + ty)) * 6144 + 3 * (s0 + tx);
    op[0] = h; op[1] = h; op[2] = l;
}

// ---------------------------------------------------------------------------
// FMA-pipe exp for x <= 0 (MUFU EX2 is quarter-rate on B300).
// ---------------------------------------------------------------------------
__device__ __forceinline__ float fexp(float x) {
    float y = x * 1.4426950408889634f;
    float n = floorf(y);
    float f = y - n;
    float p = 0.000154035304f;
    p = fmaf(p, f, 0.00133335581f);
    p = fmaf(p, f, 0.00961812910f);
    p = fmaf(p, f, 0.0555041087f);
    p = fmaf(p, f, 0.240226507f);
    p = fmaf(p, f, 0.693147180f);
    p = fmaf(p, f, 1.0f);
    int ni = (int)n;
    if (ni < -126) return 0.f;
    return p * __int_as_float((ni + 127) << 23);
}

// ---------------------------------------------------------------------------
// causal softmax: reads fp32 scores, writes A-split bf16 att3 (zeros tail)
// ---------------------------------------------------------------------------
__global__ void softmax_split_kernel(const float* __restrict__ att,
                                     __nv_bfloat16* __restrict__ att3, int Tn)
{
    __shared__ float buf[2048];
    __shared__ float red[256];
    const int row = blockIdx.x;
    const int t = row % Tn;
    const float* p = att + (long long)row * Tn;
    const int tid = threadIdx.x;
    const int len = t + 1;

    float m = -1e30f;
    for (int s = tid; s < len; s += 256) { float v = p[s]; buf[s] = v; m = fmaxf(m, v); }
    red[tid] = m; __syncthreads();
    for (int off = 128; off > 0; off >>= 1) {
        if (tid < off) red[tid] = fmaxf(red[tid], red[tid + off]);
        __syncthreads();
    }
    m = red[0]; __syncthreads();

    float sum = 0.f;
    for (int s = tid; s < len; s += 256) {
        float e = fexp(buf[s] - m);
        buf[s] = e;
        sum += e;
    }
    red[tid] = sum; __syncthreads();
    for (int off = 128; off > 0; off >>= 1) {
        if (tid < off) red[tid] += red[tid + off];
        __syncthreads();
    }
    const float inv = 1.f / red[0];
    __syncthreads();

    __nv_bfloat16* out = att3 + (long long)row * (3 * Tn);
    const int s8 = tid * 8;
    alignas(16) unsigned short sh[24];
    #pragma unroll
    for (int j = 0; j < 8; j++) {
        const int s = s8 + j;
        const float e = (s < len) ? buf[s] * inv : 0.f;
        __nv_bfloat16 h = __float2bfloat16(e);
        __nv_bfloat16 l = __float2bfloat16(e - __bfloat162float(h));
        sh[3*j] = __bfloat16_as_ushort(h);
        sh[3*j+1] = __bfloat16_as_ushort(l);
        sh[3*j+2] = __bfloat16_as_ushort(h);
    }
    __nv_bfloat16* op = out + 3 * s8;
    *(uint4*)(op)      = *(uint4*)(sh);
    *(uint4*)(op + 8)  = *(uint4*)(sh + 8);
    *(uint4*)(op + 16) = *(uint4*)(sh + 16);
}

// ---------------------------------------------------------------------------
extern "C" void kernel_launch(void* const* d_in, const int* in_sizes, int n_in,
                              void* d_out, int out_size)
{
    const float* x      = (const float*)d_in[0];
    const float* w_qkv  = (const float*)d_in[1];
    const float* b_qkv  = (const float*)d_in[2];
    const float* w_proj = (const float*)d_in[3];
    const float* b_proj = (const float*)d_in[4];
    float* out = (float*)d_out;

    float *att, *v;
    __nv_bfloat16 *x3, *wqkv3, *wproj3, *q3, *k3, *vt3, *att3, *o3;
    cudaGetSymbolAddress((void**)&att, g_att);
    cudaGetSymbolAddress((void**)&v,   g_v);
    cudaGetSymbolAddress((void**)&x3,    g_x3);
    cudaGetSymbolAddress((void**)&wqkv3, g_wqkv3);
    cudaGetSymbolAddress((void**)&wproj3,g_wproj3);
    cudaGetSymbolAddress((void**)&q3,    g_q3);
    cudaGetSymbolAddress((void**)&k3,    g_k3);
    cudaGetSymbolAddress((void**)&vt3,   g_vt3);
    cudaGetSymbolAddress((void**)&att3,  g_att3);
    cudaGetSymbolAddress((void**)&o3,    g_o3);

    const float inv_sqrt_c = 0.03125f;

    // split the raw inputs
    split3_kernel<1><<<(M * (C / 8) + 255) / 256, 256>>>(x, x3, M, C, C);
    split3_kernel<0><<<(3 * C * (C / 8) + 255) / 256, 256>>>(w_qkv, wqkv3, 3 * C, C, C);
    split3_kernel<0><<<(C * (C / 8) + 255) / 256, 256>>>(w_proj, wproj3, C, C, C);

    // 1) qkv GEMM, fused epilogue -> q3 (A-split) / k3 (B-split) / v (fp32)
    hmma_gemm<<<dim3(3 * C / 128, M / 128, 1), 128>>>(
        x3, wqkv3, nullptr, q3, k3, v,
        K3C, K3C, 0, K3C, 0, 0, 0,
        1.f, b_qkv, 0, 0, K3C, 2);

    // transpose-split v -> vt3 (B-type)
    transpose_split3_kernel<<<dim3(T / 32, C / 32, Bb), dim3(32, 32)>>>(v, vt3);

    // 2) scores = (q @ k^T) / sqrt(C), causal tile-skip, fp32 out
    hmma_gemm<<<dim3(T / 128, T / 128, Bb), 128>>>(
        q3, k3, att, nullptr, nullptr, nullptr,
        K3C, K3C, T, 0,
        (long long)T * K3C, (long long)T * K3C, (long long)T * T,
        inv_sqrt_c, nullptr, 1, 0, K3C, 0);

    // 3) softmax fused with A-split -> att3 (zeros masked tail)
    softmax_split_kernel<<<M, 256>>>(att, att3, T);

    // 4) o = att @ V  (k-limited), fused epilogue -> o3 (A-split)
    hmma_gemm<<<dim3(C / 128, T / 128, Bb), 128>>>(
        att3, vt3, nullptr, o3, nullptr, nullptr,
        K3T, K3T, 0, K3C,
        (long long)T * K3T, (long long)C * K3T, (long long)T * K3C,
        1.f, nullptr, 0, 1, K3T, 1);

    // 5) out = o @ w_proj^T + b_proj   (fp32 out)
    hmma_gemm<<<dim3(C / 128, M / 128, 1), 128>>>(
        o3, wproj3, out, nullptr, nullptr, nullptr,
        K3C, K3C, C, 0, 0, 0, 0,
        1.f, b_proj, 0, 0, K3C, 0);
}

// round 7
// speedup vs baseline: 2.5477x; 1.1181x over previous
#include <cuda_runtime.h>
#include <cuda_bf16.h>
#include <math.h>

// ---------------------------------------------------------------------------
// Causal self-attention block via mma.sync (HMMA bf16) on sm_103.
// fp32 emulation by 3-term bf16 split along K (k' = 3k + {0,1,2}):
//   A3 = (Ah, Al, Ah),  B3 = (Bh, Bh, Bl)  -> drops only Al*Bl (~2^-18).
// R7: 64-element k-chunks (one barrier per 64k), 2-stage 64KB smem pipeline,
// explicit ldmatrix fragment double-buffering across k16 slices.
// ---------------------------------------------------------------------------

static const int Bb = 4, T = 2048, C = 1024;
static const int M = Bb * T;          // 8192
static const int K3C = 3 * C;         // 3072
static const int K3T = 3 * T;         // 6144

// fp32 intermediates
__device__ float g_att[(size_t)4 * 2048 * 2048];
__device__ float g_v  [(size_t)8192 * 1024];
// 3-split bf16 operands
__device__ __nv_bfloat16 g_x3    [(size_t)8192 * 3072];
__device__ __nv_bfloat16 g_wqkv3 [(size_t)3072 * 3072];
__device__ __nv_bfloat16 g_wproj3[(size_t)1024 * 3072];
__device__ __nv_bfloat16 g_q3    [(size_t)8192 * 3072];
__device__ __nv_bfloat16 g_k3    [(size_t)8192 * 3072];
__device__ __nv_bfloat16 g_vt3   [(size_t)4 * 1024 * 6144];
__device__ __nv_bfloat16 g_att3  [(size_t)8192 * 6144];
__device__ __nv_bfloat16 g_o3    [(size_t)8192 * 3072];

__device__ __forceinline__ void cp_async16(unsigned s, const void* g) {
    asm volatile("cp.async.cg.shared.global [%0], [%1], 16;"
        :: "r"(s), "l"(__cvta_generic_to_global(g)) : "memory");
}
__device__ __forceinline__ void ldm4(unsigned* r, unsigned addr) {
    asm volatile("ldmatrix.sync.aligned.m8n8.x4.shared.b16 {%0,%1,%2,%3}, [%4];"
        : "=r"(r[0]), "=r"(r[1]), "=r"(r[2]), "=r"(r[3]) : "r"(addr));
}
__device__ __forceinline__ void mma16816(float* d, const unsigned* a,
                                         unsigned b0, unsigned b1) {
    asm volatile(
        "mma.sync.aligned.m16n8k16.row.col.f32.bf16.bf16.f32 "
        "{%0,%1,%2,%3}, {%4,%5,%6,%7}, {%8,%9}, {%0,%1,%2,%3};"
        : "+f"(d[0]), "+f"(d[1]), "+f"(d[2]), "+f"(d[3])
        : "r"(a[0]), "r"(a[1]), "r"(a[2]), "r"(a[3]), "r"(b0), "r"(b1));
}

// pack (vx, vy) as 3-term split -> 3 u32 stores (12B)
// satype=1: (h,l,h)(h2,l2,h2)   satype=0: (h,h,l)(h2,h2,l2)
__device__ __forceinline__ void store3(__nv_bfloat16* p, float vx, float vy,
                                       int satype) {
    __nv_bfloat16 hx = __float2bfloat16(vx);
    __nv_bfloat16 lx = __float2bfloat16(vx - __bfloat162float(hx));
    __nv_bfloat16 hy = __float2bfloat16(vy);
    __nv_bfloat16 ly = __float2bfloat16(vy - __bfloat162float(hy));
    unsigned hxu = __bfloat16_as_ushort(hx), lxu = __bfloat16_as_ushort(lx);
    unsigned hyu = __bfloat16_as_ushort(hy), lyu = __bfloat16_as_ushort(ly);
    unsigned u0, u1, u2;
    if (satype) { u0 = hxu | (lxu << 16); u1 = hxu | (hyu << 16); u2 = lyu | (hyu << 16); }
    else        { u0 = hxu | (hxu << 16); u1 = lxu | (hyu << 16); u2 = hyu | (lyu << 16); }
    unsigned* up = (unsigned*)p;
    up[0] = u0; up[1] = u1; up[2] = u2;
}

#define BKC 64            // bf16 elements per k-chunk (4 k16 slices)
#define STAGE_BYTES 32768 // A 16KB + B 16KB
#define GEMM_SMEM 65536   // 2 stages

// SW128 on 128-byte rows: chunk index c (0..7) -> c ^ (r & 7)
#define SWB(r, c) ((unsigned)((r) * 128 + ((((c) ^ ((r) & 7)) & 7) << 4)))

// ---------------------------------------------------------------------------
// D[M,N] = alpha * A3[M,K'] . B3[N,K']^T (+ bias)   (both operands K-major)
// 128 threads, 4 warps, 64x64 warp tiles over a 128x128 CTA tile.
// emode 0: fp32 out (Cf, ldcf)          [scores, proj]
// emode 1: A-split bf16 out (C3a, ldc3) [att@V -> o3]
// emode 2: qkv triple: col<1024 -> q3 (A-split), <2048 -> k3 (B-split),
//          else fp32 -> Cv (ld 1024). bias indexed by absolute col.
// ---------------------------------------------------------------------------
__global__ void __launch_bounds__(128, 2)
hmma_gemm(const __nv_bfloat16* __restrict__ A, const __nv_bfloat16* __restrict__ B,
          float* __restrict__ Cf, __nv_bfloat16* __restrict__ C3a,
          __nv_bfloat16* __restrict__ C3b, float* __restrict__ Cv,
          int lda, int ldb, int ldcf, int ldc3,
          long long sA, long long sB, long long sC,
          float alpha, const float* __restrict__ bias,
          int causal_skip, int klimit, int K3, int emode)
{
    const int row0 = blockIdx.y * 128;
    const int col0 = blockIdx.x * 128;
    if (causal_skip && col0 > row0) return;              // strictly-upper tiles
    const int kend = klimit ? min(K3, 3 * (row0 + 128)) : K3;
    const int nch = kend / BKC;

    A += (long long)blockIdx.z * sA + (long long)row0 * lda;
    B += (long long)blockIdx.z * sB + (long long)col0 * ldb;

    extern __shared__ __align__(128) unsigned char smem[];
    const unsigned sb = (unsigned)__cvta_generic_to_shared(smem);

    const int tid = threadIdx.x;
    const int lane = tid & 31;
    const int wid = tid >> 5;          // 0..3
    const int wm = wid >> 1;           // 0..1 -> 64-row half
    const int wn = wid & 1;            // 0..1 -> 64-col half

    float acc[4][8][4];
    #pragma unroll
    for (int i = 0; i < 4; i++)
        #pragma unroll
        for (int j = 0; j < 8; j++)
            #pragma unroll
            for (int k = 0; k < 4; k++) acc[i][j][k] = 0.f;

    // tile loader: 128 rows x 64 bf16 per operand, 8 x 16B per row
    const int lr0 = tid >> 3;        // advances by 16 per iter
    const int lc  = tid & 7;
    auto load_tile = [&](int st, int kc) {
        const unsigned sA_ = sb + st * STAGE_BYTES;
        const unsigned sB_ = sA_ + 16384;
        #pragma unroll
        for (int p = 0; p < 8; p++) {
            const int r = lr0 + p * 16;
            const unsigned so = SWB(r, lc);
            cp_async16(sA_ + so, A + (long long)r * lda + kc + lc * 8);
            cp_async16(sB_ + so, B + (long long)r * ldb + kc + lc * 8);
        }
        asm volatile("cp.async.commit_group;" ::: "memory");
    };

    // fragment loaders for k16 slice j (0..3)
    auto ld_afr = [&](unsigned sA_, int j, unsigned af[4][4]) {
        const int ch = 2 * j + (lane >> 4);
        #pragma unroll
        for (int mb = 0; mb < 4; mb++) {
            const int mr = wm * 64 + mb * 16 + (lane & 15);
            ldm4(af[mb], sA_ + SWB(mr, ch));
        }
    };
    auto ld_bfr = [&](unsigned sB_, int j, unsigned bf[4][4]) {
        const int ch = 2 * j + (lane >> 4);
        #pragma unroll
        for (int nbb = 0; nbb < 4; nbb++) {
            const int nr = wn * 64 + nbb * 16 + (lane & 15);
            ldm4(bf[nbb], sB_ + SWB(nr, ch));
        }
    };

    auto compute = [&](int st) {
        const unsigned sA_ = sb + st * STAGE_BYTES;
        const unsigned sB_ = sA_ + 16384;
        unsigned af[2][4][4], bf[2][4][4];
        ld_afr(sA_, 0, af[0]);
        ld_bfr(sB_, 0, bf[0]);
        #pragma unroll
        for (int j = 0; j < 4; j++) {
            const int cur = j & 1;
            if (j < 3) {                       // prefetch next slice's frags
                ld_afr(sA_, j + 1, af[cur ^ 1]);
                ld_bfr(sB_, j + 1, bf[cur ^ 1]);
            }
            #pragma unroll
            for (int mb = 0; mb < 4; mb++)
                #pragma unroll
                for (int nbb = 0; nbb < 4; nbb++) {
                    mma16816(acc[mb][nbb * 2 + 0], af[cur][mb],
                             bf[cur][nbb][0], bf[cur][nbb][2]);
                    mma16816(acc[mb][nbb * 2 + 1], af[cur][mb],
                             bf[cur][nbb][1], bf[cur][nbb][3]);
                }
        }
    };

    load_tile(0, 0);
    for (int i = 0; i < nch; i++) {
        asm volatile("cp.async.wait_group 0;" ::: "memory");
        __syncthreads();
        if (i + 1 < nch) load_tile((i + 1) & 1, (i + 1) * BKC);
        compute(i & 1);
        __syncthreads();
    }

    // ----- epilogue -----
    __nv_bfloat16* d3 = 0;
    int satype = 1, colr = col0;
    float* df = 0;
    int ldf = ldcf;
    if (emode == 0) {
        df = Cf + (long long)blockIdx.z * sC;
    } else if (emode == 1) {
        d3 = C3a + (long long)blockIdx.z * sC;
    } else {                                  // qkv triple
        if (col0 < 1024)      { d3 = C3a; satype = 1; colr = col0; }
        else if (col0 < 2048) { d3 = C3b; satype = 0; colr = col0 - 1024; }
        else                  { df = Cv; ldf = 1024; colr = col0 - 2048; }
    }

    const int cbase = wn * 64 + 2 * (lane & 3);
    #pragma unroll
    for (int mb = 0; mb < 4; mb++) {
        #pragma unroll
        for (int half = 0; half < 2; half++) {
            const int r = row0 + wm * 64 + mb * 16 + (lane >> 2) + half * 8;
            #pragma unroll
            for (int nb = 0; nb < 8; nb++) {
                const int cr = colr + cbase + nb * 8;    // region-relative (even)
                const int ca = col0 + cbase + nb * 8;    // absolute (bias)
                float vx = acc[mb][nb][half * 2 + 0] * alpha;
                float vy = acc[mb][nb][half * 2 + 1] * alpha;
                if (bias) { vx += bias[ca]; vy += bias[ca + 1]; }
                if (d3) store3(d3 + (long long)r * ldc3 + 3 * cr, vx, vy, satype);
                else    *(float2*)(df + (long long)r * ldf + cr) = make_float2(vx, vy);
            }
        }
    }
}

// ---------------------------------------------------------------------------
// fp32 -> 3-term interleaved bf16 split (standalone; inputs only)
// ---------------------------------------------------------------------------
template <int ATYPE>
__global__ void split3_kernel(const float* __restrict__ in,
                              __nv_bfloat16* __restrict__ out,
                              int R, int Cin, int ld)
{
    const int c8n = Cin >> 3;
    long long idx = (long long)blockIdx.x * blockDim.x + threadIdx.x;
    if (idx >= (long long)R * c8n) return;
    const int r = (int)(idx / c8n);
    const int c = (int)(idx - (long long)r * c8n) * 8;

    const float4 v0 = *(const float4*)(in + (long long)r * ld + c);
    const float4 v1 = *(const float4*)(in + (long long)r * ld + c + 4);
    float f[8] = {v0.x, v0.y, v0.z, v0.w, v1.x, v1.y, v1.z, v1.w};

    alignas(16) unsigned short s[24];
    #pragma unroll
    for (int j = 0; j < 8; j++) {
        __nv_bfloat16 h = __float2bfloat16(f[j]);
        __nv_bfloat16 l = __float2bfloat16(f[j] - __bfloat162float(h));
        unsigned short hu = __bfloat16_as_ushort(h);
        unsigned short lu = __bfloat16_as_ushort(l);
        if (ATYPE) { s[3*j] = hu; s[3*j+1] = lu; s[3*j+2] = hu; }
        else       { s[3*j] = hu; s[3*j+1] = hu; s[3*j+2] = lu; }
    }
    __nv_bfloat16* op = out + (long long)r * (3 * Cin) + 3 * c;
    *(uint4*)(op)      = *(uint4*)(s);
    *(uint4*)(op + 8)  = *(uint4*)(s + 8);
    *(uint4*)(op + 16) = *(uint4*)(s + 16);
}

// V[s,c] fp32 [8192,1024] -> vt3[b][c][3s+{0,1,2}] = (hi,hi,lo)
__global__ void transpose_split3_kernel(const float* __restrict__ v,
                                        __nv_bfloat16* __restrict__ vt3)
{
    __shared__ float tile[32][33];
    const int b = blockIdx.z;
    const int s0 = blockIdx.x * 32, c0 = blockIdx.y * 32;
    const int tx = threadIdx.x, ty = threadIdx.y;
    tile[ty][tx] = v[((long long)(b * 2048 + s0 + ty)) * 1024 + c0 + tx];
    __syncthreads();
    const float val = tile[tx][ty];
    __nv_bfloat16 h = __float2bfloat16(val);
    __nv_bfloat16 l = __float2bfloat16(val - __bfloat162float(h));
    __nv_bfloat16* op = vt3 + ((long long)(b * 1024 + c0 + ty)) * 6144 + 3 * (s0 + tx);
    op[0] = h; op[1] = h; op[2] = l;
}

// ---------------------------------------------------------------------------
// FMA-pipe exp for x <= 0 (MUFU EX2 is quarter-rate on B300).
// ---------------------------------------------------------------------------
__device__ __forceinline__ float fexp(float x) {
    float y = x * 1.4426950408889634f;
    float n = floorf(y);
    float f = y - n;
    float p = 0.000154035304f;
    p = fmaf(p, f, 0.00133335581f);
    p = fmaf(p, f, 0.00961812910f);
    p = fmaf(p, f, 0.0555041087f);
    p = fmaf(p, f, 0.240226507f);
    p = fmaf(p, f, 0.693147180f);
    p = fmaf(p, f, 1.0f);
    int ni = (int)n;
    if (ni < -126) return 0.f;
    return p * __int_as_float((ni + 127) << 23);
}

// ---------------------------------------------------------------------------
// causal softmax: reads fp32 scores, writes A-split bf16 att3 (zeros tail)
// ---------------------------------------------------------------------------
__global__ void softmax_split_kernel(const float* __restrict__ att,
                                     __nv_bfloat16* __restrict__ att3, int Tn)
{
    __shared__ float buf[2048];
    __shared__ float red[256];
    const int row = blockIdx.x;
    const int t = row % Tn;
    const float* p = att + (long long)row * Tn;
    const int tid = threadIdx.x;
    const int len = t + 1;

    float m = -1e30f;
    for (int s = tid; s < len; s += 256) { float v = p[s]; buf[s] = v; m = fmaxf(m, v); }
    red[tid] = m; __syncthreads();
    for (int off = 128; off > 0; off >>= 1) {
        if (tid < off) red[tid] = fmaxf(red[tid], red[tid + off]);
        __syncthreads();
    }
    m = red[0]; __syncthreads();

    float sum = 0.f;
    for (int s = tid; s < len; s += 256) {
        float e = fexp(buf[s] - m);
        buf[s] = e;
        sum += e;
    }
    red[tid] = sum; __syncthreads();
    for (int off = 128; off > 0; off >>= 1) {
        if (tid < off) red[tid] += red[tid + off];
        __syncthreads();
    }
    const float inv = 1.f / red[0];
    __syncthreads();

    __nv_bfloat16* out = att3 + (long long)row * (3 * Tn);
    const int s8 = tid * 8;
    alignas(16) unsigned short sh[24];
    #pragma unroll
    for (int j = 0; j < 8; j++) {
        const int s = s8 + j;
        const float e = (s < len) ? buf[s] * inv : 0.f;
        __nv_bfloat16 h = __float2bfloat16(e);
        __nv_bfloat16 l = __float2bfloat16(e - __bfloat162float(h));
        sh[3*j] = __bfloat16_as_ushort(h);
        sh[3*j+1] = __bfloat16_as_ushort(l);
        sh[3*j+2] = __bfloat16_as_ushort(h);
    }
    __nv_bfloat16* op = out + 3 * s8;
    *(uint4*)(op)      = *(uint4*)(sh);
    *(uint4*)(op + 8)  = *(uint4*)(sh + 8);
    *(uint4*)(op + 16) = *(uint4*)(sh + 16);
}

// ---------------------------------------------------------------------------
extern "C" void kernel_launch(void* const* d_in, const int* in_sizes, int n_in,
                              void* d_out, int out_size)
{
    const float* x      = (const float*)d_in[0];
    const float* w_qkv  = (const float*)d_in[1];
    const float* b_qkv  = (const float*)d_in[2];
    const float* w_proj = (const float*)d_in[3];
    const float* b_proj = (const float*)d_in[4];
    float* out = (float*)d_out;

    float *att, *v;
    __nv_bfloat16 *x3, *wqkv3, *wproj3, *q3, *k3, *vt3, *att3, *o3;
    cudaGetSymbolAddress((void**)&att, g_att);
    cudaGetSymbolAddress((void**)&v,   g_v);
    cudaGetSymbolAddress((void**)&x3,    g_x3);
    cudaGetSymbolAddress((void**)&wqkv3, g_wqkv3);
    cudaGetSymbolAddress((void**)&wproj3,g_wproj3);
    cudaGetSymbolAddress((void**)&q3,    g_q3);
    cudaGetSymbolAddress((void**)&k3,    g_k3);
    cudaGetSymbolAddress((void**)&vt3,   g_vt3);
    cudaGetSymbolAddress((void**)&att3,  g_att3);
    cudaGetSymbolAddress((void**)&o3,    g_o3);

    cudaFuncSetAttribute(hmma_gemm,
        cudaFuncAttributeMaxDynamicSharedMemorySize, GEMM_SMEM);

    const float inv_sqrt_c = 0.03125f;

    // split the raw inputs
    split3_kernel<1><<<(M * (C / 8) + 255) / 256, 256>>>(x, x3, M, C, C);
    split3_kernel<0><<<(3 * C * (C / 8) + 255) / 256, 256>>>(w_qkv, wqkv3, 3 * C, C, C);
    split3_kernel<0><<<(C * (C / 8) + 255) / 256, 256>>>(w_proj, wproj3, C, C, C);

    // 1) qkv GEMM, fused epilogue -> q3 (A-split) / k3 (B-split) / v (fp32)
    hmma_gemm<<<dim3(3 * C / 128, M / 128, 1), 128, GEMM_SMEM>>>(
        x3, wqkv3, nullptr, q3, k3, v,
        K3C, K3C, 0, K3C, 0, 0, 0,
        1.f, b_qkv, 0, 0, K3C, 2);

    // transpose-split v -> vt3 (B-type)
    transpose_split3_kernel<<<dim3(T / 32, C / 32, Bb), dim3(32, 32)>>>(v, vt3);

    // 2) scores = (q @ k^T) / sqrt(C), causal tile-skip, fp32 out
    hmma_gemm<<<dim3(T / 128, T / 128, Bb), 128, GEMM_SMEM>>>(
        q3, k3, att, nullptr, nullptr, nullptr,
        K3C, K3C, T, 0,
        (long long)T * K3C, (long long)T * K3C, (long long)T * T,
        inv_sqrt_c, nullptr, 1, 0, K3C, 0);

    // 3) softmax fused with A-split -> att3 (zeros masked tail)
    softmax_split_kernel<<<M, 256>>>(att, att3, T);

    // 4) o = att @ V  (k-limited), fused epilogue -> o3 (A-split)
    hmma_gemm<<<dim3(C / 128, T / 128, Bb), 128, GEMM_SMEM>>>(
        att3, vt3, nullptr, o3, nullptr, nullptr,
        K3T, K3T, 0, K3C,
        (long long)T * K3T, (long long)C * K3T, (long long)T * K3C,
        1.f, nullptr, 0, 1, K3T, 1);

    // 5) out = o @ w_proj^T + b_proj   (fp32 out)
    hmma_gemm<<<dim3(C / 128, M / 128, 1), 128, GEMM_SMEM>>>(
        o3, wproj3, out, nullptr, nullptr, nullptr,
        K3C, K3C, C, 0, 0, 0, 0,
        1.f, b_proj, 0, 0, K3C, 0);
}